// round 7
// baseline (speedup 1.0000x reference)
#include <cuda_runtime.h>
#include <cuda_bf16.h>

// Per-channel class frequencies (compile-time constants from the reference).
__constant__ float c_W[23] = {
    0.0012597430655963838f, 0.0004919313290455535f, 0.0021106513104319356f,
    0.0007678117365508301f, 0.004719881670572202f,  0.000372272357115554f,
    0.029090425620315438f,  0.010056339432617042f,  0.0034817436971298467f,
    0.0003057951504877765f, 0.003995280118329428f,  8.808229878180519e-05f,
    0.012070598793438699f,  0.016788818533845208f,  0.0017832510677901316f,
    0.0008758371973209686f, 0.0005933090691529143f, 0.0031992155689617922f,
    0.003212511010287348f,  0.0016685778863572154f, 0.0009356666832859684f,
    0.0010985358395240233f, 0.00103372056306194f
};

// stride = NBLOCKS*NTHREADS must be ≡ 0 (mod 23) so per-thread channels are
// loop-invariant (8-wide units: 8*stride ≡ 0 mod 23 as well).
#define NBLOCKS 1173
#define NTHREADS 256
#define LN2F 0.6931471805599453f

// Pinned prefix in 8-element units (x: 32 B + labels: 32 B = 64 B per unit).
// Multiple of 23 so loop-2 channel phase matches. ~100 MB pinned in L2.
#define N_PIN_U8 (23 * 68000)     // 1,564,000 units = 100.1 MB

__device__ float    g_part[NBLOCKS];
__device__ unsigned g_count = 0;

// 32-byte loads with L2 eviction-priority hints (sm_103a requires .v4.b64).
__device__ __forceinline__ void ld32_last(const void* p,
    unsigned long long& a, unsigned long long& b,
    unsigned long long& c, unsigned long long& d) {
    asm volatile("ld.global.nc.L2::evict_last.v4.b64 {%0,%1,%2,%3}, [%4];"
                 : "=l"(a), "=l"(b), "=l"(c), "=l"(d) : "l"(p));
}
__device__ __forceinline__ void ld32_first(const void* p,
    unsigned long long& a, unsigned long long& b,
    unsigned long long& c, unsigned long long& d) {
    asm volatile("ld.global.nc.L2::evict_first.v4.b64 {%0,%1,%2,%3}, [%4];"
                 : "=l"(a), "=l"(b), "=l"(c), "=l"(d) : "l"(p));
}

#define LO_F(u) __uint_as_float((unsigned)(u))
#define HI_F(u) __uint_as_float((unsigned)((u) >> 32))
#define LO_I(u) ((int)(unsigned)(u))
#define HI_I(u) ((int)(unsigned)((u) >> 32))

__global__ __launch_bounds__(NTHREADS, 8)
void bce_fused_kernel(const float* __restrict__ x,
                      const int*   __restrict__ l,
                      int n_u8, int n_pin, int rem, int tail_base,
                      float* __restrict__ out, float inv_n) {
    __shared__ float  s_w0[23];   // ln2*(W+1)   : weight when label==0
    __shared__ float  s_w1[23];   // ln2*(1+1/W) : weight when label==1
    __shared__ float  s_part[NTHREADS / 32];
    __shared__ double s_dpart[NTHREADS / 32];
    __shared__ bool   s_is_last;

    const int t = threadIdx.x;
    if (t < 23) {
        float w = c_W[t];
        s_w0[t] = LN2F * (w + 1.0f);
        s_w1[t] = LN2F * (1.0f + __frcp_rn(w));
    }
    __syncthreads();

    const int stride = NBLOCKS * NTHREADS;   // ≡ 0 (mod 23)
    const int gtid   = blockIdx.x * NTHREADS + t;

    // Fixed channels for this thread's 8-element window.
    int ch[8];
    ch[0] = (int)((8ll * (long long)gtid) % 23);
    #pragma unroll
    for (int j = 1; j < 8; ++j) { ch[j] = ch[j-1] + 1; if (ch[j] >= 23) ch[j] -= 23; }

    float w0r[8], w1r[8];
    #pragma unroll
    for (int j = 0; j < 8; ++j) { w0r[j] = s_w0[ch[j]]; w1r[j] = s_w1[ch[j]]; }

    float acc = 0.0f;

    // Loop 1: pinned region — resident in L2 across graph replays.
    for (int v = gtid; v < n_pin; v += stride) {
        unsigned long long xa, xb, xc, xd, la, lb, lc, ld_;
        ld32_last(x + 8ll * v, xa, xb, xc, xd);
        ld32_last(l + 8ll * v, la, lb, lc, ld_);
        float xs[8] = { LO_F(xa), HI_F(xa), LO_F(xb), HI_F(xb),
                        LO_F(xc), HI_F(xc), LO_F(xd), HI_F(xd) };
        int   ls[8] = { LO_I(la), HI_I(la), LO_I(lb), HI_I(lb),
                        LO_I(lc), HI_I(lc), LO_I(ld_), HI_I(ld_) };
        #pragma unroll
        for (int j = 0; j < 8; ++j) {
            bool p = ls[j] > 0;
            acc = fmaf(p ? w1r[j] : w0r[j],
                       -__log2f(p ? xs[j] : 1.0f - xs[j]), acc);
        }
    }

    // Loop 2: streaming region — evict_first keeps pinned lines resident.
    for (int v = n_pin + gtid; v < n_u8; v += stride) {
        unsigned long long xa, xb, xc, xd, la, lb, lc, ld_;
        ld32_first(x + 8ll * v, xa, xb, xc, xd);
        ld32_first(l + 8ll * v, la, lb, lc, ld_);
        float xs[8] = { LO_F(xa), HI_F(xa), LO_F(xb), HI_F(xb),
                        LO_F(xc), HI_F(xc), LO_F(xd), HI_F(xd) };
        int   ls[8] = { LO_I(la), HI_I(la), LO_I(lb), HI_I(lb),
                        LO_I(lc), HI_I(lc), LO_I(ld_), HI_I(ld_) };
        #pragma unroll
        for (int j = 0; j < 8; ++j) {
            bool p = ls[j] > 0;
            acc = fmaf(p ? w1r[j] : w0r[j],
                       -__log2f(p ? xs[j] : 1.0f - xs[j]), acc);
        }
    }

    // Scalar tail (n % 8 elements; 0 for 23e6 but kept for generality).
    if (gtid < rem) {
        int   i   = tail_base + gtid;
        int   lab = l[i];
        float xv  = x[i];
        int   c   = i % 23;
        bool  pos = (lab > 0);
        acc = fmaf(pos ? s_w1[c] : s_w0[c],
                   -__log2f(pos ? xv : 1.0f - xv), acc);
    }

    // Intra-block reduce (f32).
    #pragma unroll
    for (int o = 16; o > 0; o >>= 1)
        acc += __shfl_down_sync(0xffffffffu, acc, o);

    const int lane = t & 31, wid = t >> 5;
    if (lane == 0) s_part[wid] = acc;
    __syncthreads();

    if (t == 0) {
        float b = 0.0f;
        #pragma unroll
        for (int w = 0; w < NTHREADS / 32; ++w) b += s_part[w];
        g_part[blockIdx.x] = b;
        __threadfence();
        unsigned ticket = atomicInc(&g_count, NBLOCKS - 1); // wraps to 0
        s_is_last = (ticket == NBLOCKS - 1);
    }
    __syncthreads();

    // Last block: deterministic final reduction in double.
    if (s_is_last) {
        __threadfence();
        double dsum = 0.0;
        for (int i = t; i < NBLOCKS; i += NTHREADS)
            dsum += (double)g_part[i];
        #pragma unroll
        for (int o = 16; o > 0; o >>= 1)
            dsum += __shfl_down_sync(0xffffffffu, dsum, o);
        if (lane == 0) s_dpart[wid] = dsum;
        __syncthreads();
        if (t == 0) {
            double tot = 0.0;
            #pragma unroll
            for (int w = 0; w < NTHREADS / 32; ++w) tot += s_dpart[w];
            out[0] = (float)(tot * (double)inv_n);
        }
    }
}

extern "C" void kernel_launch(void* const* d_in, const int* in_sizes, int n_in,
                              void* d_out, int out_size) {
    const float* x = (const float*)d_in[0];
    const int*   l = (const int*)d_in[1];
    float* out = (float*)d_out;

    long long n = (long long)in_sizes[0];   // total elements (B*C) = 23e6
    int n_u8 = (int)(n >> 3);               // 8-element units
    int rem = (int)(n & 7);
    int tail_base = n_u8 << 3;

    int n_pin = N_PIN_U8 < n_u8 ? N_PIN_U8 : n_u8;

    bce_fused_kernel<<<NBLOCKS, NTHREADS>>>(
        x, l, n_u8, n_pin, rem, tail_base, out, 1.0f / (float)n);
}

// round 8
// speedup vs baseline: 1.2201x; 1.2201x over previous
#include <cuda_runtime.h>
#include <cuda_bf16.h>

// Per-channel class frequencies (compile-time constants from the reference).
__constant__ float c_W[23] = {
    0.0012597430655963838f, 0.0004919313290455535f, 0.0021106513104319356f,
    0.0007678117365508301f, 0.004719881670572202f,  0.000372272357115554f,
    0.029090425620315438f,  0.010056339432617042f,  0.0034817436971298467f,
    0.0003057951504877765f, 0.003995280118329428f,  8.808229878180519e-05f,
    0.012070598793438699f,  0.016788818533845208f,  0.0017832510677901316f,
    0.0008758371973209686f, 0.0005933090691529143f, 0.0031992155689617922f,
    0.003212511010287348f,  0.0016685778863572154f, 0.0009356666832859684f,
    0.0010985358395240233f, 0.00103372056306194f
};

// 1184 = 8 CTAs x 148 SMs: perfectly balanced single wave (R2's winning grid).
#define NBLOCKS 1184
#define NTHREADS 256
#define LN2F 0.6931471805599453f

// Scratch (no allocations allowed). Every g_part slot is written every run;
// g_count self-wraps to 0 via atomicInc -> graph-replay safe.
__device__ float    g_part[NBLOCKS];
__device__ unsigned g_count = 0;

__global__ __launch_bounds__(NTHREADS, 8)
void bce_fused_kernel(const float4* __restrict__ x4,
                      const int4*   __restrict__ l4,
                      int n_vec, int rem,
                      const float* __restrict__ x_tail,
                      const int*   __restrict__ l_tail,
                      int tail_base,
                      float* __restrict__ out, float inv_n) {
    __shared__ float  s_w0[23];   // ln2*(W+1)   : weight when label==0
    __shared__ float  s_w1[23];   // ln2*(1+1/W) : weight when label==1
    __shared__ float  s_part[NTHREADS / 32];
    __shared__ double s_dpart[NTHREADS / 32];
    __shared__ bool   s_is_last;

    const int t = threadIdx.x;
    if (t < 23) {
        float w = c_W[t];
        s_w0[t] = LN2F * (w + 1.0f);
        s_w1[t] = LN2F * (1.0f + __frcp_rn(w));
    }
    __syncthreads();

    const int stride = NBLOCKS * NTHREADS;
    const int gtid   = blockIdx.x * NTHREADS + t;

    // Channel of the first element of this thread's first vector, and the
    // per-iteration advance (4*stride mod 23).
    int c_base = (int)((4ll * (long long)gtid) % 23);
    const int d = (int)((4ll * (long long)stride) % 23);

    float acc = 0.0f;

    // Plain grid-stride loop, compiler-chosen unroll (R2's winning schedule).
    for (int v = gtid; v < n_vec; v += stride) {
        float4 xv = __ldg(&x4[v]);
        int4   lv = __ldg(&l4[v]);

        int c = c_base;
        c_base += d; if (c_base >= 23) c_base -= 23;

        float xs[4] = { xv.x, xv.y, xv.z, xv.w };
        int   ls[4] = { lv.x, lv.y, lv.z, lv.w };
        #pragma unroll
        for (int j = 0; j < 4; ++j) {
            bool  pos = (ls[j] > 0);
            float arg = pos ? xs[j] : (1.0f - xs[j]);
            const float* tab = pos ? s_w1 : s_w0;   // one LDS per element
            acc = fmaf(tab[c], -__log2f(arg), acc);
            c = (c == 22) ? 0 : (c + 1);
        }
    }

    // Scalar tail (n % 4 elements; 0 for B*C = 23e6 but kept for generality).
    if (gtid < rem) {
        int   i   = tail_base + gtid;
        int   lab = __ldg(&l_tail[gtid]);
        float xv  = __ldg(&x_tail[gtid]);
        int   c   = i % 23;
        bool  pos = (lab > 0);
        float arg = pos ? xv : (1.0f - xv);
        const float* tab = pos ? s_w1 : s_w0;
        acc = fmaf(tab[c], -__log2f(arg), acc);
    }

    // Intra-block reduce (f32).
    #pragma unroll
    for (int o = 16; o > 0; o >>= 1)
        acc += __shfl_down_sync(0xffffffffu, acc, o);

    const int lane = t & 31, wid = t >> 5;
    if (lane == 0) s_part[wid] = acc;
    __syncthreads();

    if (t == 0) {
        float b = 0.0f;
        #pragma unroll
        for (int w = 0; w < NTHREADS / 32; ++w) b += s_part[w];
        g_part[blockIdx.x] = b;
        __threadfence();
        unsigned ticket = atomicInc(&g_count, NBLOCKS - 1); // wraps to 0
        s_is_last = (ticket == NBLOCKS - 1);
    }
    __syncthreads();

    // Last block: deterministic final reduction in double.
    if (s_is_last) {
        __threadfence();
        double dsum = 0.0;
        for (int i = t; i < NBLOCKS; i += NTHREADS)
            dsum += (double)g_part[i];
        #pragma unroll
        for (int o = 16; o > 0; o >>= 1)
            dsum += __shfl_down_sync(0xffffffffu, dsum, o);
        if (lane == 0) s_dpart[wid] = dsum;
        __syncthreads();
        if (t == 0) {
            double tot = 0.0;
            #pragma unroll
            for (int w = 0; w < NTHREADS / 32; ++w) tot += s_dpart[w];
            out[0] = (float)(tot * (double)inv_n);
        }
    }
}

extern "C" void kernel_launch(void* const* d_in, const int* in_sizes, int n_in,
                              void* d_out, int out_size) {
    const float* x = (const float*)d_in[0];
    const int*   l = (const int*)d_in[1];
    float* out = (float*)d_out;

    long long n = (long long)in_sizes[0];   // total elements (B*C) = 23e6
    int n_vec = (int)(n >> 2);
    int rem = (int)(n & 3);
    int tail_base = n_vec << 2;

    bce_fused_kernel<<<NBLOCKS, NTHREADS>>>(
        (const float4*)x, (const int4*)l, n_vec, rem,
        x + (long long)tail_base, l + (long long)tail_base, tail_base,
        out, 1.0f / (float)n);
}